// round 7
// baseline (speedup 1.0000x reference)
#include <cuda_runtime.h>
#include <math_constants.h>

// MultiSimilarityLoss: sim_mat [8192,8192] f32, labels [8192] i64-or-i32 -> scalar f32
//
// R7: single fused kernel.
//  - Per-CTA label dtype detection (warp ballot on odd 32-bit words) + direct
//    raw-label reads (longlong2 / int4), raw buffer L1-resident across CTAs.
//  - Poison: same-labeled elements x = s - 4 (in [-5,-3]).
//    * min over ALL x == hardest positive; max over ALL x == hardest negative.
//  - 256 thr x 32 elems, 32 KB smem value buffer, __launch_bounds__(256,5).
//  - Dense pass2: LDS.128 + 4x(FFMA + MUFU.EX2 + FSETP + @FADD).
//  - Fused final reduction: completion counter, last CTA sums deterministically
//    and resets the counter (graph-replay safe).

constexpr int BN        = 8192;
constexpr int NTHREADS  = 256;
constexpr int PER       = BN / NTHREADS;   // 32
constexpr int NVEC      = PER / 4;         // 8 float4 slots per thread
constexpr int NWARPS    = NTHREADS / 32;   // 8

constexpr float ONE_MEPS = 1.0f - 1e-5f;          // pos threshold on s
constexpr float POISON   = 4.0f;
constexpr float PB       = ONE_MEPS - POISON;     // poisoned pos boundary ~ -3.00001
// exp(40(s-0.5)) = exp2(x*K40 + C40)
constexpr float K40 = 57.706801635558536f;        //  40*log2(e)
constexpr float C40 = -28.853400817779268f;       // -20*log2(e)
// exp(-2(s-0.5)) with s = x+4  ->  exp2(x*KP + CP)
constexpr float KP  = -2.885390081777927f;        //  -2*log2(e)
constexpr float CP  = -10.098865286222744f;       //  -7*log2(e)

__device__ float g_row_loss[BN];
__device__ int   g_done = 0;

__device__ __forceinline__ float ex2(float a) {
    float r;
    asm("ex2.approx.ftz.f32 %0, %1;" : "=f"(r) : "f"(a));
    return r;
}

// Streaming (evict-first) 128-bit load: touched exactly once.
__device__ __forceinline__ float4 ldcs4(const float4* p) {
    float4 r;
    asm("ld.global.cs.v4.f32 {%0,%1,%2,%3}, [%4];"
        : "=f"(r.x), "=f"(r.y), "=f"(r.z), "=f"(r.w) : "l"(p));
    return r;
}

// Pass 1 body, templated on raw label dtype. Fills vsm with poisoned values,
// returns thread-local min/max over x.
template <bool IS64>
__device__ __forceinline__ void pass1(
    const float4* __restrict__ srow4, const void* __restrict__ labels_raw,
    int my_label, int tid, float4* vsm, float& mn_out, float& mx_out)
{
    const int4*      lab4 = reinterpret_cast<const int4*>(labels_raw);
    const longlong2* lab2 = reinterpret_cast<const longlong2*>(labels_raw);

    float mn = CUDART_INF_F;    // min over all x == hardest positive (poisoned)
    float mx = -CUDART_INF_F;   // max over all x == hardest negative

    #pragma unroll
    for (int c = 0; c < 2; c++) {
        float4 a[4];
        int    lv[4][4];
        #pragma unroll
        for (int k = 0; k < 4; k++) a[k] = ldcs4(srow4 + tid + (c * 4 + k) * NTHREADS);
        #pragma unroll
        for (int k = 0; k < 4; k++) {
            int j4 = tid + (c * 4 + k) * NTHREADS;   // float4 slot: elems 4*j4..4*j4+3
            if (IS64) {
                longlong2 p0 = __ldg(lab2 + 2 * j4);
                longlong2 p1 = __ldg(lab2 + 2 * j4 + 1);
                lv[k][0] = (int)p0.x; lv[k][1] = (int)p0.y;
                lv[k][2] = (int)p1.x; lv[k][3] = (int)p1.y;
            } else {
                int4 p = __ldg(lab4 + j4);
                lv[k][0] = p.x; lv[k][1] = p.y; lv[k][2] = p.z; lv[k][3] = p.w;
            }
        }
        #pragma unroll
        for (int k = 0; k < 4; k++) {
            float sv[4] = {a[k].x, a[k].y, a[k].z, a[k].w};
            float xv[4];
            #pragma unroll
            for (int e = 0; e < 4; e++) {
                float x = sv[e];
                if (lv[k][e] == my_label) x -= POISON;   // ISETP + @FADD
                xv[e] = x;
                mn = fminf(mn, x);                       // FMNMX
                mx = fmaxf(mx, x);                       // FMNMX
            }
            vsm[(c * 4 + k) * NTHREADS + tid] = make_float4(xv[0], xv[1], xv[2], xv[3]);
        }
    }
    mn_out = mn; mx_out = mx;
}

__global__ __launch_bounds__(NTHREADS, 5) void row_kernel(
    const float* __restrict__ sim, const void* __restrict__ labels_raw,
    float* __restrict__ out)
{
    const int row  = blockIdx.x;
    const int tid  = threadIdx.x;
    const int lane = tid & 31;
    const int warp = tid >> 5;

    __shared__ float4 vsm[NVEC * NTHREADS];            // 32 KB poisoned values
    __shared__ float s_mn[NWARPS], s_mx[NWARPS];
    __shared__ float s_minall, s_maxneg;
    __shared__ float s_ps[NWARPS], s_ns[NWARPS];
    __shared__ int   s_last;

    // ---- per-warp dtype detection (uniform result, no sync needed) ----
    // int64 labels < 1024 => every odd 32-bit word zero. 32 sampled words:
    // P(false positive for int32) = (1/1024)^32 ~ 0.
    const unsigned* w = (const unsigned*)labels_raw;
    unsigned f = __ldg(&w[2 * lane + 1]);
    bool is64 = (__ballot_sync(0xffffffffu, f != 0u) == 0u);

    const int my_label = is64 ? (int)__ldg(&((const long long*)labels_raw)[row])
                              : __ldg(&((const int*)labels_raw)[row]);

    const float4* __restrict__ srow4 = reinterpret_cast<const float4*>(sim + (size_t)row * BN);

    float mn, mx;
    if (is64) pass1<true >(srow4, labels_raw, my_label, tid, vsm, mn, mx);
    else      pass1<false>(srow4, labels_raw, my_label, tid, vsm, mn, mx);
    const float my_mn = mn;                            // thread-local pos trigger

    // ---- block reduce min_all / max_neg ----
    #pragma unroll
    for (int o = 16; o; o >>= 1) {
        mn = fminf(mn, __shfl_xor_sync(0xffffffffu, mn, o));
        mx = fmaxf(mx, __shfl_xor_sync(0xffffffffu, mx, o));
    }
    if (lane == 0) { s_mn[warp] = mn; s_mx[warp] = mx; }
    __syncthreads();
    if (warp == 0) {
        float a = (lane < NWARPS) ? s_mn[lane] : CUDART_INF_F;
        float b = (lane < NWARPS) ? s_mx[lane] : -CUDART_INF_F;
        #pragma unroll
        for (int o = 4; o; o >>= 1) {
            a = fminf(a, __shfl_xor_sync(0xffffffffu, a, o));
            b = fmaxf(b, __shfl_xor_sync(0xffffffffu, b, o));
        }
        if (lane == 0) { s_minall = a; s_maxneg = b; }
    }
    __syncthreads();

    const float pb_up = __int_as_float(__float_as_int(PB) - 1);  // next float toward 0
    // Positive exists iff min_all < pb_up. Then hardest positive (poisoned) =
    // min_all, and sel_neg threshold tn = min_pos - 0.1 = min_all + 3.9.
    const float min_all = s_minall;
    const float tn = (min_all < pb_up) ? (min_all + 3.9f) : CUDART_INF_F;

    // ---- dense neg pass from smem: LDS.128 + 4x(FFMA+MUFU+FSETP+@FADD) ----
    float ns0 = 0.0f, ns1 = 0.0f, ns2 = 0.0f, ns3 = 0.0f;
    #pragma unroll
    for (int j = 0; j < NVEC; j++) {
        float4 x = vsm[j * NTHREADS + tid];
        float e0 = ex2(fmaf(x.x, K40, C40));
        float e1 = ex2(fmaf(x.y, K40, C40));
        float e2 = ex2(fmaf(x.z, K40, C40));
        float e3 = ex2(fmaf(x.w, K40, C40));
        if (x.x > tn) ns0 += e0;    // poisoned x <= -3 < tn always (tn >= -1.1)
        if (x.y > tn) ns1 += e1;
        if (x.z > tn) ns2 += e2;
        if (x.w > tn) ns3 += e3;
    }
    float neg_sum = (ns0 + ns1) + (ns2 + ns3);

    // ---- rare pos pass (this thread owns >= 1 positive) ----
    float pos_sum = 0.0f;
    if (my_mn < pb_up) {
        // sel_pos: x <= PB (positive) AND s - 0.1 < max_neg i.e. x < max_neg - 3.9
        float tp = fminf(pb_up, s_maxneg - 3.9f);
        #pragma unroll
        for (int j = 0; j < NVEC; j++) {
            float4 x = vsm[j * NTHREADS + tid];
            float e0 = ex2(fmaf(x.x, KP, CP));   // exp(-2(s-0.5)) on poisoned x
            float e1 = ex2(fmaf(x.y, KP, CP));
            float e2 = ex2(fmaf(x.z, KP, CP));
            float e3 = ex2(fmaf(x.w, KP, CP));
            if (x.x < tp) pos_sum += e0;
            if (x.y < tp) pos_sum += e1;
            if (x.z < tp) pos_sum += e2;
            if (x.w < tp) pos_sum += e3;
        }
    }

    // ---- block reduce the two sums, write row loss ----
    #pragma unroll
    for (int o = 16; o; o >>= 1) {
        pos_sum += __shfl_xor_sync(0xffffffffu, pos_sum, o);
        neg_sum += __shfl_xor_sync(0xffffffffu, neg_sum, o);
    }
    if (lane == 0) { s_ps[warp] = pos_sum; s_ns[warp] = neg_sum; }
    __syncthreads();
    if (tid == 0) {
        float ps = 0.0f, ns = 0.0f;
        #pragma unroll
        for (int wi = 0; wi < NWARPS; wi++) { ps += s_ps[wi]; ns += s_ns[wi]; }
        float loss = 0.0f;
        if (ps > 0.0f && ns > 0.0f)      // exp > 0: ps>0 <=> any(sel_pos)
            loss = log1pf(ps) * 0.5f + log1pf(ns) * 0.025f;
        g_row_loss[row] = loss;
        __threadfence();
        int old = atomicAdd(&g_done, 1);
        s_last = (old == BN - 1) ? 1 : 0;
    }
    __syncthreads();

    // ---- last CTA: deterministic final reduction + counter reset ----
    if (s_last) {
        __threadfence();                 // acquire: see all rows' losses
        float sum = 0.0f;
        #pragma unroll
        for (int i = 0; i < BN / NTHREADS; i++) sum += g_row_loss[tid + i * NTHREADS];
        #pragma unroll
        for (int o = 16; o; o >>= 1) sum += __shfl_xor_sync(0xffffffffu, sum, o);
        if (lane == 0) s_ps[warp] = sum;
        __syncthreads();
        if (tid == 0) {
            float t = 0.0f;
            #pragma unroll
            for (int wi = 0; wi < NWARPS; wi++) t += s_ps[wi];
            out[0] = t / (float)BN;
            g_done = 0;                  // reset for next graph replay
        }
    }
}

extern "C" void kernel_launch(void* const* d_in, const int* in_sizes, int n_in,
                              void* d_out, int out_size) {
    // Guard against input ordering: sim has BN*BN elements, labels BN.
    const void* p0 = d_in[0];
    const void* p1 = d_in[1];
    const float* sim;
    const void*  labels;
    if (in_sizes[0] == BN) { labels = p0; sim = (const float*)p1; }
    else                   { sim = (const float*)p0; labels = p1; }
    float* out = (float*)d_out;

    row_kernel<<<BN, NTHREADS>>>(sim, labels, out);
}